// round 1
// baseline (speedup 1.0000x reference)
#include <cuda_runtime.h>
#include <cuda_bf16.h>

#define T_TOK 8192
#define D_DIM 1024
#define E_EXP 8
#define F_DIM 512
#define NPAIR (T_TOK * 2)

// ---- scratch (device globals; no allocations allowed) ----
__device__ int   g_topk_idx[NPAIR];
__device__ float g_topk_p[NPAIR];
__device__ int   g_cnt[E_EXP];
__device__ int   g_off[E_EXP];
__device__ int   g_cur[E_EXP];
__device__ int   g_pair_token[NPAIR];
__device__ int   g_pair_pos[NPAIR];               // (t,k) -> pair position
__device__ float g_H[(size_t)NPAIR * F_DIM];      // 32 MB
__device__ float g_O[(size_t)NPAIR * D_DIM];      // 64 MB

__global__ void init_kernel() {
    if (threadIdx.x < E_EXP) g_cnt[threadIdx.x] = 0;
}

// One block (128 threads) per token: 8 dot products of length D, softmax-top2.
__global__ void router_kernel(const float* __restrict__ x,
                              const float* __restrict__ wr) {
    int t = blockIdx.x;
    int tid = threadIdx.x;
    float acc[E_EXP];
#pragma unroll
    for (int e = 0; e < E_EXP; e++) acc[e] = 0.f;
    const float* xr = x + (size_t)t * D_DIM;
    for (int i = tid; i < D_DIM; i += 128) {
        float xv = xr[i];
#pragma unroll
        for (int e = 0; e < E_EXP; e++)
            acc[e] += xv * wr[e * D_DIM + i];
    }
    __shared__ float sh[E_EXP][128];
#pragma unroll
    for (int e = 0; e < E_EXP; e++) sh[e][tid] = acc[e];
    __syncthreads();
    for (int s = 64; s > 0; s >>= 1) {
        if (tid < s) {
#pragma unroll
            for (int e = 0; e < E_EXP; e++) sh[e][tid] += sh[e][tid + s];
        }
        __syncthreads();
    }
    if (tid == 0) {
        float l[E_EXP];
#pragma unroll
        for (int e = 0; e < E_EXP; e++) l[e] = sh[e][0];
        int i1 = 0;
#pragma unroll
        for (int e = 1; e < E_EXP; e++) if (l[e] > l[i1]) i1 = e;
        int i2 = (i1 == 0) ? 1 : 0;
#pragma unroll
        for (int e = 0; e < E_EXP; e++) if (e != i1 && l[e] > l[i2]) i2 = e;
        // renormalized top-2 softmax probs: p1 = 1/(1+exp(l2-l1))
        float ex = __expf(l[i2] - l[i1]);   // <= 1
        float inv = 1.f / (1.f + ex);
        g_topk_idx[t * 2 + 0] = i1; g_topk_p[t * 2 + 0] = inv;
        g_topk_idx[t * 2 + 1] = i2; g_topk_p[t * 2 + 1] = ex * inv;
        atomicAdd(&g_cnt[i1], 1);
        atomicAdd(&g_cnt[i2], 1);
    }
}

__global__ void prefix_kernel() {
    if (threadIdx.x == 0) {
        int acc = 0;
        for (int e = 0; e < E_EXP; e++) {
            g_off[e] = acc;
            g_cur[e] = acc;
            acc += g_cnt[e];
        }
    }
}

__global__ void scatter_kernel() {
    int t = blockIdx.x * blockDim.x + threadIdx.x;
    if (t >= T_TOK) return;
#pragma unroll
    for (int k = 0; k < 2; k++) {
        int e = g_topk_idx[t * 2 + k];
        int pos = atomicAdd(&g_cur[e], 1);
        g_pair_token[pos] = t;
        g_pair_pos[t * 2 + k] = pos;
    }
}

// GEMM1: H[pair, F] = silu(X_gathered @ Wg_e) * (X_gathered @ Wu_e)
// Tile 64(M:pairs) x 64(N:F) x 16(K:D). 256 threads, 4x4 microtile, two accumulator sets.
__global__ void __launch_bounds__(256) gemm1_kernel(const float* __restrict__ x,
                                                    const float* __restrict__ wg,
                                                    const float* __restrict__ wu) {
    int e = blockIdx.z;
    int cnt = g_cnt[e];
    int m0 = blockIdx.y * 64;
    if (m0 >= cnt) return;
    int n0 = blockIdx.x * 64;
    int base = g_off[e];

    __shared__ float As[16][64];
    __shared__ float Bg[16][64];
    __shared__ float Bu[16][64];
    __shared__ int toks[64];

    int tid = threadIdx.x;
    if (tid < 64) {
        int m = m0 + tid;
        toks[tid] = (m < cnt) ? g_pair_token[base + m] : 0;
    }
    __syncthreads();

    int tx = tid & 15, ty = tid >> 4;
    float accg[4][4] = {}, accu[4][4] = {};
    const float* wgb = wg + (size_t)e * D_DIM * F_DIM;
    const float* wub = wu + (size_t)e * D_DIM * F_DIM;

    int am = tid >> 2;
    int akq = (tid & 3) * 4;
    int bk = tid >> 4;
    int bn = (tid & 15) * 4;
    const float* xrow = x + (size_t)toks[am] * D_DIM;

    for (int k0 = 0; k0 < D_DIM; k0 += 16) {
        float4 va = *(const float4*)(xrow + k0 + akq);
        As[akq + 0][am] = va.x; As[akq + 1][am] = va.y;
        As[akq + 2][am] = va.z; As[akq + 3][am] = va.w;
        float4 vg = *(const float4*)(wgb + (size_t)(k0 + bk) * F_DIM + n0 + bn);
        *(float4*)&Bg[bk][bn] = vg;
        float4 vu = *(const float4*)(wub + (size_t)(k0 + bk) * F_DIM + n0 + bn);
        *(float4*)&Bu[bk][bn] = vu;
        __syncthreads();
#pragma unroll
        for (int kk = 0; kk < 16; kk++) {
            float4 a4 = *(const float4*)&As[kk][ty * 4];
            float4 g4 = *(const float4*)&Bg[kk][tx * 4];
            float4 u4 = *(const float4*)&Bu[kk][tx * 4];
            float av[4] = {a4.x, a4.y, a4.z, a4.w};
            float gv[4] = {g4.x, g4.y, g4.z, g4.w};
            float uv[4] = {u4.x, u4.y, u4.z, u4.w};
#pragma unroll
            for (int i = 0; i < 4; i++)
#pragma unroll
                for (int j = 0; j < 4; j++) {
                    accg[i][j] += av[i] * gv[j];
                    accu[i][j] += av[i] * uv[j];
                }
        }
        __syncthreads();
    }
#pragma unroll
    for (int i = 0; i < 4; i++) {
        int m = m0 + ty * 4 + i;
        if (m < cnt) {
            float4 o;
            float h[4];
#pragma unroll
            for (int j = 0; j < 4; j++) {
                float g = accg[i][j];
                float s = g / (1.f + __expf(-g));
                h[j] = s * accu[i][j];
            }
            o.x = h[0]; o.y = h[1]; o.z = h[2]; o.w = h[3];
            *(float4*)(g_H + (size_t)(base + m) * F_DIM + n0 + tx * 4) = o;
        }
    }
}

// GEMM2: O[pair, D] = H[pair, F] @ Wd_e   (prob applied in combine)
__global__ void __launch_bounds__(256) gemm2_kernel(const float* __restrict__ wd) {
    int e = blockIdx.z;
    int cnt = g_cnt[e];
    int m0 = blockIdx.y * 64;
    if (m0 >= cnt) return;
    int n0 = blockIdx.x * 64;
    int base = g_off[e];

    __shared__ float As[16][64];
    __shared__ float Bs[16][64];

    int tid = threadIdx.x;
    int tx = tid & 15, ty = tid >> 4;
    float acc[4][4] = {};
    const float* wdb = wd + (size_t)e * F_DIM * D_DIM;

    int am = tid >> 2;
    int akq = (tid & 3) * 4;
    int bk = tid >> 4;
    int bn = (tid & 15) * 4;
    int mm = m0 + am;
    int arow = base + ((mm < cnt) ? mm : 0);
    const float* hrow = g_H + (size_t)arow * F_DIM;

    for (int k0 = 0; k0 < F_DIM; k0 += 16) {
        float4 va = *(const float4*)(hrow + k0 + akq);
        As[akq + 0][am] = va.x; As[akq + 1][am] = va.y;
        As[akq + 2][am] = va.z; As[akq + 3][am] = va.w;
        float4 vb = *(const float4*)(wdb + (size_t)(k0 + bk) * D_DIM + n0 + bn);
        *(float4*)&Bs[bk][bn] = vb;
        __syncthreads();
#pragma unroll
        for (int kk = 0; kk < 16; kk++) {
            float4 a4 = *(const float4*)&As[kk][ty * 4];
            float4 b4 = *(const float4*)&Bs[kk][tx * 4];
            float av[4] = {a4.x, a4.y, a4.z, a4.w};
            float bv[4] = {b4.x, b4.y, b4.z, b4.w};
#pragma unroll
            for (int i = 0; i < 4; i++)
#pragma unroll
                for (int j = 0; j < 4; j++)
                    acc[i][j] += av[i] * bv[j];
        }
        __syncthreads();
    }
#pragma unroll
    for (int i = 0; i < 4; i++) {
        int m = m0 + ty * 4 + i;
        if (m < cnt) {
            float4 o;
            o.x = acc[i][0]; o.y = acc[i][1]; o.z = acc[i][2]; o.w = acc[i][3];
            *(float4*)(g_O + (size_t)(base + m) * D_DIM + n0 + tx * 4) = o;
        }
    }
}

// out[t] = p0 * O[pos0] + p1 * O[pos1]   (fully overwrites d_out)
__global__ void combine_kernel(float* __restrict__ out) {
    int idx = blockIdx.x * blockDim.x + threadIdx.x;   // over T*D/4
    int t = idx / (D_DIM / 4);
    int j4 = (idx % (D_DIM / 4)) * 4;
    float p0 = g_topk_p[t * 2 + 0];
    float p1 = g_topk_p[t * 2 + 1];
    int q0 = g_pair_pos[t * 2 + 0];
    int q1 = g_pair_pos[t * 2 + 1];
    float4 a = *(const float4*)(g_O + (size_t)q0 * D_DIM + j4);
    float4 b = *(const float4*)(g_O + (size_t)q1 * D_DIM + j4);
    float4 o;
    o.x = p0 * a.x + p1 * b.x;
    o.y = p0 * a.y + p1 * b.y;
    o.z = p0 * a.z + p1 * b.z;
    o.w = p0 * a.w + p1 * b.w;
    *(float4*)(out + (size_t)t * D_DIM + j4) = o;
}

extern "C" void kernel_launch(void* const* d_in, const int* in_sizes, int n_in,
                              void* d_out, int out_size) {
    const float* x  = (const float*)d_in[0];   // hidden_states [4,2048,1024]
    const float* wr = (const float*)d_in[1];   // router_weight [8,1024]
    const float* wg = (const float*)d_in[2];   // w_gate [8,1024,512]
    const float* wu = (const float*)d_in[3];   // w_up   [8,1024,512]
    const float* wd = (const float*)d_in[4];   // w_down [8,512,1024]
    float* out = (float*)d_out;

    init_kernel<<<1, 32>>>();
    router_kernel<<<T_TOK, 128>>>(x, wr);
    prefix_kernel<<<1, 32>>>();
    scatter_kernel<<<T_TOK / 256, 256>>>();

    dim3 g1(F_DIM / 64, NPAIR / 64, E_EXP);    // (8, 256, 8)
    gemm1_kernel<<<g1, 256>>>(x, wg, wu);

    dim3 g2(D_DIM / 64, NPAIR / 64, E_EXP);    // (16, 256, 8)
    gemm2_kernel<<<g2, 256>>>(wd);

    combine_kernel<<<(T_TOK * D_DIM / 4) / 256, 256>>>(out);
}

// round 5
// speedup vs baseline: 1.0710x; 1.0710x over previous
#include <cuda_runtime.h>
#include <cuda_bf16.h>
#include <stdint.h>

#define T_TOK 8192
#define D_DIM 1024
#define E_EXP 8
#define F_DIM 512
#define NPAIR (T_TOK * 2)

// ---------------- device scratch ----------------
__device__ int   g_topk_idx[NPAIR];
__device__ float g_topk_p[NPAIR];
__device__ int   g_cnt[E_EXP];
__device__ int   g_off[E_EXP];
__device__ int   g_cur[E_EXP];
__device__ int   g_pair_token[NPAIR];
__device__ int   g_pair_pos[NPAIR];
__device__ float g_H[(size_t)(NPAIR + 128) * F_DIM];   // 33 MB
__device__ float g_O[(size_t)NPAIR * D_DIM];           // 64 MB

// ---------------- mma helper (the ONLY new HW feature vs R1) ----------------
__device__ __forceinline__ void mma16816(float* c, const uint32_t* a, const uint32_t* b) {
    asm volatile(
        "mma.sync.aligned.m16n8k16.row.col.f32.bf16.bf16.f32 "
        "{%0,%1,%2,%3}, {%4,%5,%6,%7}, {%8,%9}, {%0,%1,%2,%3};"
        : "+f"(c[0]), "+f"(c[1]), "+f"(c[2]), "+f"(c[3])
        : "r"(a[0]), "r"(a[1]), "r"(a[2]), "r"(a[3]), "r"(b[0]), "r"(b[1]));
}
__device__ __forceinline__ void split_bf16(float v, unsigned short* hi, unsigned short* lo) {
    __nv_bfloat16 h = __float2bfloat16_rn(v);
    __nv_bfloat16 l = __float2bfloat16_rn(v - __bfloat162float(h));
    *hi = *(unsigned short*)&h;
    *lo = *(unsigned short*)&l;
}

// ---------------- small kernels (identical to proven R1) ----------------
__global__ void init_kernel() {
    if (threadIdx.x < E_EXP) g_cnt[threadIdx.x] = 0;
}

__global__ void router_kernel(const float* __restrict__ x,
                              const float* __restrict__ wr) {
    int t = blockIdx.x;
    int tid = threadIdx.x;
    float acc[E_EXP];
#pragma unroll
    for (int e = 0; e < E_EXP; e++) acc[e] = 0.f;
    const float* xr = x + (size_t)t * D_DIM;
    for (int i = tid; i < D_DIM; i += 128) {
        float xv = xr[i];
#pragma unroll
        for (int e = 0; e < E_EXP; e++) acc[e] += xv * wr[e * D_DIM + i];
    }
    __shared__ float sh[E_EXP][128];
#pragma unroll
    for (int e = 0; e < E_EXP; e++) sh[e][tid] = acc[e];
    __syncthreads();
    for (int s = 64; s > 0; s >>= 1) {
        if (tid < s) {
#pragma unroll
            for (int e = 0; e < E_EXP; e++) sh[e][tid] += sh[e][tid + s];
        }
        __syncthreads();
    }
    if (tid == 0) {
        float l[E_EXP];
#pragma unroll
        for (int e = 0; e < E_EXP; e++) l[e] = sh[e][0];
        int i1 = 0;
#pragma unroll
        for (int e = 1; e < E_EXP; e++) if (l[e] > l[i1]) i1 = e;
        int i2 = (i1 == 0) ? 1 : 0;
#pragma unroll
        for (int e = 0; e < E_EXP; e++) if (e != i1 && l[e] > l[i2]) i2 = e;
        float ex = __expf(l[i2] - l[i1]);
        float inv = 1.f / (1.f + ex);
        g_topk_idx[t * 2 + 0] = i1; g_topk_p[t * 2 + 0] = inv;
        g_topk_idx[t * 2 + 1] = i2; g_topk_p[t * 2 + 1] = ex * inv;
        atomicAdd(&g_cnt[i1], 1);
        atomicAdd(&g_cnt[i2], 1);
    }
}

__global__ void prefix_kernel() {
    if (threadIdx.x == 0) {
        int acc = 0;
        for (int e = 0; e < E_EXP; e++) { g_off[e] = acc; g_cur[e] = acc; acc += g_cnt[e]; }
    }
}

__global__ void scatter_kernel() {
    int t = blockIdx.x * blockDim.x + threadIdx.x;
    if (t >= T_TOK) return;
#pragma unroll
    for (int k = 0; k < 2; k++) {
        int e = g_topk_idx[t * 2 + k];
        int pos = atomicAdd(&g_cur[e], 1);
        g_pair_token[pos] = t;
        g_pair_pos[t * 2 + k] = pos;
    }
}

// ---------------- GEMM1: H = silu(X Wg) * (X Wu) ----------------
// CTA: M=128 pairs, 64 F-cols (gate rows 0-63, up rows 64-127 of B smem).
// 8 warps: wm in [0,4) x wn in [0,2). Warp: 32 M-rows x 32 F-cols, gate+up.
// K-stage 32, single buffered, fragments via direct LDS (no ldmatrix/cp.async).
__global__ void __launch_bounds__(256) gemm1_mma(const float* __restrict__ x,
                                                 const float* __restrict__ wg,
                                                 const float* __restrict__ wu) {
    int e = blockIdx.z;
    int cnt = g_cnt[e];
    int m0 = blockIdx.y * 128;
    if (m0 >= cnt) return;
    int base = g_off[e];
    int f0 = blockIdx.x * 64;

    __shared__ unsigned short As_h[128][34], As_l[128][34];
    __shared__ unsigned short Bs_h[128][34], Bs_l[128][34];
    __shared__ int toks[128];

    int tid = threadIdx.x;
    int lid = tid & 31, wid = tid >> 5;
    int wm = wid >> 1, wn = wid & 1;

    if (tid < 128) {
        int m = m0 + tid;
        toks[tid] = g_pair_token[base + ((m < cnt) ? m : 0)];
    }
    __syncthreads();

    float acc_g[2][4][4], acc_u[2][4][4];
#pragma unroll
    for (int a = 0; a < 2; a++)
#pragma unroll
        for (int b = 0; b < 4; b++)
#pragma unroll
            for (int c = 0; c < 4; c++) { acc_g[a][b][c] = 0.f; acc_u[a][b][c] = 0.f; }

    for (int s = 0; s < D_DIM / 32; ++s) {
        int k0 = s * 32;
        // ---- stage A: 128 x 32 fp32, split to bf16 hi/lo ----
#pragma unroll
        for (int it = 0; it < 16; ++it) {
            int idx = tid + it * 256;
            int m = idx >> 5, k = idx & 31;
            float v = x[(size_t)toks[m] * D_DIM + k0 + k];
            split_bf16(v, &As_h[m][k], &As_l[m][k]);
        }
        // ---- stage B: gate(64f) + up(64f) x 32k, native [k][f] layout ----
#pragma unroll
        for (int it = 0; it < 16; ++it) {
            int idx = tid + it * 256;
            int half = idx >> 11, rem = idx & 2047;
            int k = rem >> 6, fl = rem & 63;
            const float* w = half ? wu : wg;
            float v = w[((size_t)e * D_DIM + k0 + k) * F_DIM + f0 + fl];
            split_bf16(v, &Bs_h[half * 64 + fl][k], &Bs_l[half * 64 + fl][k]);
        }
        __syncthreads();
        // ---- compute: 2 k-halves of 16 ----
#pragma unroll
        for (int kk = 0; kk < 2; ++kk) {
            int kc = kk * 16 + (lid & 3) * 2;
            uint32_t ah[2][4], al[2][4];
#pragma unroll
            for (int mi = 0; mi < 2; ++mi) {
                int r = wm * 32 + mi * 16 + (lid >> 2);
                ah[mi][0] = *(uint32_t*)&As_h[r][kc];
                ah[mi][1] = *(uint32_t*)&As_h[r + 8][kc];
                ah[mi][2] = *(uint32_t*)&As_h[r][kc + 8];
                ah[mi][3] = *(uint32_t*)&As_h[r + 8][kc + 8];
                al[mi][0] = *(uint32_t*)&As_l[r][kc];
                al[mi][1] = *(uint32_t*)&As_l[r + 8][kc];
                al[mi][2] = *(uint32_t*)&As_l[r][kc + 8];
                al[mi][3] = *(uint32_t*)&As_l[r + 8][kc + 8];
            }
#pragma unroll
            for (int j = 0; j < 4; ++j) {
                int ng = wn * 32 + j * 8 + (lid >> 2);
                uint32_t bgh[2], bgl[2], buh[2], bul[2];
                bgh[0] = *(uint32_t*)&Bs_h[ng][kc];
                bgh[1] = *(uint32_t*)&Bs_h[ng][kc + 8];
                bgl[0] = *(uint32_t*)&Bs_l[ng][kc];
                bgl[1] = *(uint32_t*)&Bs_l[ng][kc + 8];
                buh[0] = *(uint32_t*)&Bs_h[ng + 64][kc];
                buh[1] = *(uint32_t*)&Bs_h[ng + 64][kc + 8];
                bul[0] = *(uint32_t*)&Bs_l[ng + 64][kc];
                bul[1] = *(uint32_t*)&Bs_l[ng + 64][kc + 8];
#pragma unroll
                for (int mi = 0; mi < 2; ++mi) {
                    mma16816(acc_g[mi][j], ah[mi], bgh);
                    mma16816(acc_g[mi][j], ah[mi], bgl);
                    mma16816(acc_g[mi][j], al[mi], bgh);
                    mma16816(acc_u[mi][j], ah[mi], buh);
                    mma16816(acc_u[mi][j], ah[mi], bul);
                    mma16816(acc_u[mi][j], al[mi], buh);
                }
            }
        }
        __syncthreads();
    }

    // ---- epilogue: silu(g)*u in registers, write H fp32 ----
#pragma unroll
    for (int mi = 0; mi < 2; ++mi) {
#pragma unroll
        for (int j = 0; j < 4; ++j) {
            int row = m0 + wm * 32 + mi * 16 + (lid >> 2);
            int col = f0 + wn * 32 + j * 8 + (lid & 3) * 2;
#pragma unroll
            for (int half = 0; half < 2; ++half) {
                int r = row + half * 8;
                if (r < cnt) {
                    float g0 = acc_g[mi][j][half * 2 + 0];
                    float g1 = acc_g[mi][j][half * 2 + 1];
                    float u0 = acc_u[mi][j][half * 2 + 0];
                    float u1 = acc_u[mi][j][half * 2 + 1];
                    float2 h;
                    h.x = u0 * g0 / (1.f + __expf(-g0));
                    h.y = u1 * g1 / (1.f + __expf(-g1));
                    *(float2*)&g_H[(size_t)(base + r) * F_DIM + col] = h;
                }
            }
        }
    }
}

// ---------------- GEMM2: O = H @ Wd (Wd native [k][n]) ----------------
// CTA: M=128 x N=128, 8 warps (4m x 2n), warp 32x64. K-stage 32, 16 stages.
__global__ void __launch_bounds__(256) gemm2_mma(const float* __restrict__ wd) {
    int e = blockIdx.z;
    int cnt = g_cnt[e];
    int m0 = blockIdx.y * 128;
    if (m0 >= cnt) return;
    int base = g_off[e];
    int n0 = blockIdx.x * 128;

    __shared__ unsigned short As_h[128][34], As_l[128][34];
    __shared__ unsigned short Bs_h[128][34], Bs_l[128][34];

    int tid = threadIdx.x;
    int lid = tid & 31, wid = tid >> 5;
    int wm = wid >> 1, wn = wid & 1;

    float acc[2][8][4];
#pragma unroll
    for (int a = 0; a < 2; a++)
#pragma unroll
        for (int b = 0; b < 8; b++)
#pragma unroll
            for (int c = 0; c < 4; c++) acc[a][b][c] = 0.f;

    for (int s = 0; s < F_DIM / 32; ++s) {
        int k0 = s * 32;
#pragma unroll
        for (int it = 0; it < 16; ++it) {
            int idx = tid + it * 256;
            int m = idx >> 5, k = idx & 31;
            float v = g_H[(size_t)(base + m0 + m) * F_DIM + k0 + k];
            split_bf16(v, &As_h[m][k], &As_l[m][k]);
        }
#pragma unroll
        for (int it = 0; it < 16; ++it) {
            int idx = tid + it * 256;
            int k = idx >> 7, nl = idx & 127;
            float v = wd[((size_t)e * F_DIM + k0 + k) * D_DIM + n0 + nl];
            split_bf16(v, &Bs_h[nl][k], &Bs_l[nl][k]);
        }
        __syncthreads();
#pragma unroll
        for (int kk = 0; kk < 2; ++kk) {
            int kc = kk * 16 + (lid & 3) * 2;
            uint32_t ah[2][4], al[2][4];
#pragma unroll
            for (int mi = 0; mi < 2; ++mi) {
                int r = wm * 32 + mi * 16 + (lid >> 2);
                ah[mi][0] = *(uint32_t*)&As_h[r][kc];
                ah[mi][1] = *(uint32_t*)&As_h[r + 8][kc];
                ah[mi][2] = *(uint32_t*)&As_h[r][kc + 8];
                ah[mi][3] = *(uint32_t*)&As_h[r + 8][kc + 8];
                al[mi][0] = *(uint32_t*)&As_l[r][kc];
                al[mi][1] = *(uint32_t*)&As_l[r + 8][kc];
                al[mi][2] = *(uint32_t*)&As_l[r][kc + 8];
                al[mi][3] = *(uint32_t*)&As_l[r + 8][kc + 8];
            }
#pragma unroll
            for (int j = 0; j < 8; ++j) {
                int n = wn * 64 + j * 8 + (lid >> 2);
                uint32_t bh[2], bl[2];
                bh[0] = *(uint32_t*)&Bs_h[n][kc];
                bh[1] = *(uint32_t*)&Bs_h[n][kc + 8];
                bl[0] = *(uint32_t*)&Bs_l[n][kc];
                bl[1] = *(uint32_t*)&Bs_l[n][kc + 8];
#pragma unroll
                for (int mi = 0; mi < 2; ++mi) {
                    mma16816(acc[mi][j], ah[mi], bh);
                    mma16816(acc[mi][j], ah[mi], bl);
                    mma16816(acc[mi][j], al[mi], bh);
                }
            }
        }
        __syncthreads();
    }

#pragma unroll
    for (int mi = 0; mi < 2; ++mi) {
#pragma unroll
        for (int j = 0; j < 8; ++j) {
            int row = m0 + wm * 32 + mi * 16 + (lid >> 2);
            int col = n0 + wn * 64 + j * 8 + (lid & 3) * 2;
#pragma unroll
            for (int half = 0; half < 2; ++half) {
                int r = row + half * 8;
                if (r < cnt) {
                    float2 v = make_float2(acc[mi][j][half * 2 + 0],
                                           acc[mi][j][half * 2 + 1]);
                    *(float2*)&g_O[(size_t)(base + r) * D_DIM + col] = v;
                }
            }
        }
    }
}

// ---------------- combine (identical to proven R1) ----------------
__global__ void combine_kernel(float* __restrict__ out) {
    int idx = blockIdx.x * blockDim.x + threadIdx.x;
    int t = idx / (D_DIM / 4);
    int j4 = (idx % (D_DIM / 4)) * 4;
    float p0 = g_topk_p[t * 2 + 0];
    float p1 = g_topk_p[t * 2 + 1];
    int q0 = g_pair_pos[t * 2 + 0];
    int q1 = g_pair_pos[t * 2 + 1];
    float4 a = *(const float4*)(g_O + (size_t)q0 * D_DIM + j4);
    float4 b = *(const float4*)(g_O + (size_t)q1 * D_DIM + j4);
    float4 o;
    o.x = p0 * a.x + p1 * b.x;
    o.y = p0 * a.y + p1 * b.y;
    o.z = p0 * a.z + p1 * b.z;
    o.w = p0 * a.w + p1 * b.w;
    *(float4*)(out + (size_t)t * D_DIM + j4) = o;
}

extern "C" void kernel_launch(void* const* d_in, const int* in_sizes, int n_in,
                              void* d_out, int out_size) {
    const float* x  = (const float*)d_in[0];
    const float* wr = (const float*)d_in[1];
    const float* wg = (const float*)d_in[2];
    const float* wu = (const float*)d_in[3];
    const float* wd = (const float*)d_in[4];
    float* out = (float*)d_out;

    init_kernel<<<1, 32>>>();
    router_kernel<<<T_TOK, 128>>>(x, wr);
    prefix_kernel<<<1, 32>>>();
    scatter_kernel<<<T_TOK / 256, 256>>>();

    gemm1_mma<<<dim3(F_DIM / 64, NPAIR / 128, E_EXP), 256>>>(x, wg, wu);
    gemm2_mma<<<dim3(D_DIM / 128, NPAIR / 128, E_EXP), 256>>>(wd);

    combine_kernel<<<(T_TOK * D_DIM / 4) / 256, 256>>>(out);
}

// round 7
// speedup vs baseline: 2.1370x; 1.9953x over previous
#include <cuda_runtime.h>
#include <cuda_bf16.h>
#include <stdint.h>

#define T_TOK 8192
#define D_DIM 1024
#define E_EXP 8
#define F_DIM 512
#define NPAIR (T_TOK * 2)

// ---------------- device scratch (kept at R5's proven footprint ~101MB) ----------------
__device__ int   g_topk_idx[NPAIR];
__device__ float g_topk_p[NPAIR];
__device__ int   g_cnt[E_EXP];
__device__ int   g_off[E_EXP];
__device__ int   g_cur[E_EXP];
__device__ int   g_pair_token[NPAIR];
__device__ int   g_pair_pos[NPAIR];
__device__ float g_H[(size_t)(NPAIR + 128) * F_DIM];   // 33 MB
__device__ float g_O[(size_t)NPAIR * D_DIM];           // 64 MB

// ---------------- helpers ----------------
__device__ __forceinline__ void mma16816(float* c, const uint32_t* a, const uint32_t* b) {
    asm volatile(
        "mma.sync.aligned.m16n8k16.row.col.f32.bf16.bf16.f32 "
        "{%0,%1,%2,%3}, {%4,%5,%6,%7}, {%8,%9}, {%0,%1,%2,%3};"
        : "+f"(c[0]), "+f"(c[1]), "+f"(c[2]), "+f"(c[3])
        : "r"(a[0]), "r"(a[1]), "r"(a[2]), "r"(a[3]), "r"(b[0]), "r"(b[1]));
}

// packed split: (a,b) -> hi bf16x2 + lo bf16x2 (residual)
__device__ __forceinline__ void split2(float a, float b, uint32_t* hi, uint32_t* lo) {
    __nv_bfloat162 h = __float22bfloat162_rn(make_float2(a, b));
    float2 hf = __bfloat1622float2(h);
    __nv_bfloat162 l = __float22bfloat162_rn(make_float2(a - hf.x, b - hf.y));
    *hi = *reinterpret_cast<uint32_t*>(&h);
    *lo = *reinterpret_cast<uint32_t*>(&l);
}
__device__ __forceinline__ void split4(float4 v, uint32_t* hi2, uint32_t* lo2) {
    split2(v.x, v.y, hi2 + 0, lo2 + 0);
    split2(v.z, v.w, hi2 + 1, lo2 + 1);
}

// ---------------- small kernels (identical to proven R1/R5) ----------------
__global__ void init_kernel() {
    if (threadIdx.x < E_EXP) g_cnt[threadIdx.x] = 0;
}

__global__ void router_kernel(const float* __restrict__ x,
                              const float* __restrict__ wr) {
    int t = blockIdx.x;
    int tid = threadIdx.x;
    float acc[E_EXP];
#pragma unroll
    for (int e = 0; e < E_EXP; e++) acc[e] = 0.f;
    const float* xr = x + (size_t)t * D_DIM;
    for (int i = tid; i < D_DIM; i += 128) {
        float xv = xr[i];
#pragma unroll
        for (int e = 0; e < E_EXP; e++) acc[e] += xv * wr[e * D_DIM + i];
    }
    __shared__ float sh[E_EXP][128];
#pragma unroll
    for (int e = 0; e < E_EXP; e++) sh[e][tid] = acc[e];
    __syncthreads();
    for (int s = 64; s > 0; s >>= 1) {
        if (tid < s) {
#pragma unroll
            for (int e = 0; e < E_EXP; e++) sh[e][tid] += sh[e][tid + s];
        }
        __syncthreads();
    }
    if (tid == 0) {
        float l[E_EXP];
#pragma unroll
        for (int e = 0; e < E_EXP; e++) l[e] = sh[e][0];
        int i1 = 0;
#pragma unroll
        for (int e = 1; e < E_EXP; e++) if (l[e] > l[i1]) i1 = e;
        int i2 = (i1 == 0) ? 1 : 0;
#pragma unroll
        for (int e = 0; e < E_EXP; e++) if (e != i1 && l[e] > l[i2]) i2 = e;
        float ex = __expf(l[i2] - l[i1]);
        float inv = 1.f / (1.f + ex);
        g_topk_idx[t * 2 + 0] = i1; g_topk_p[t * 2 + 0] = inv;
        g_topk_idx[t * 2 + 1] = i2; g_topk_p[t * 2 + 1] = ex * inv;
        atomicAdd(&g_cnt[i1], 1);
        atomicAdd(&g_cnt[i2], 1);
    }
}

__global__ void prefix_kernel() {
    if (threadIdx.x == 0) {
        int acc = 0;
        for (int e = 0; e < E_EXP; e++) { g_off[e] = acc; g_cur[e] = acc; acc += g_cnt[e]; }
    }
}

__global__ void scatter_kernel() {
    int t = blockIdx.x * blockDim.x + threadIdx.x;
    if (t >= T_TOK) return;
#pragma unroll
    for (int k = 0; k < 2; k++) {
        int e = g_topk_idx[t * 2 + k];
        int pos = atomicAdd(&g_cur[e], 1);
        g_pair_token[pos] = t;
        g_pair_pos[t * 2 + k] = pos;
    }
}

// smem tile: 128 rows x 32 bf16, rows padded to 40 shorts (80B: 16B-aligned stores,
// fragment LDS verified conflict-free: banks (20r + lane&3) mod 32 all distinct)
#define PADK 40

// ---------------- GEMM1: H = silu(X Wg) * (X Wu) ----------------
// Identical structure/fragments/epilogue to R5 (proven). New: vectorized loads,
// packed converts, uint4 STS, register prefetch of next stage.
__global__ void __launch_bounds__(256) gemm1_mma(const float* __restrict__ x,
                                                 const float* __restrict__ wg,
                                                 const float* __restrict__ wu) {
    int e = blockIdx.z;
    int cnt = g_cnt[e];
    int m0 = blockIdx.y * 128;
    if (m0 >= cnt) return;
    int base = g_off[e];
    int f0 = blockIdx.x * 64;

    __shared__ unsigned short As_h[128][PADK], As_l[128][PADK];
    __shared__ unsigned short Bs_h[128][PADK], Bs_l[128][PADK];
    __shared__ int toks[128];

    int tid = threadIdx.x;
    int lid = tid & 31, wid = tid >> 5;
    int wm = wid >> 1, wn = wid & 1;

    if (tid < 128) {
        int m = m0 + tid;
        toks[tid] = g_pair_token[base + ((m < cnt) ? m : 0)];
    }
    __syncthreads();

    float acc_g[2][4][4], acc_u[2][4][4];
#pragma unroll
    for (int a = 0; a < 2; a++)
#pragma unroll
        for (int b = 0; b < 4; b++)
#pragma unroll
            for (int c = 0; c < 4; c++) { acc_g[a][b][c] = 0.f; acc_u[a][b][c] = 0.f; }

    // per-thread load mapping: one smem row, 16 of 32 k per stage
    int row0 = tid >> 1, kh = (tid & 1) * 16;
    const float* asrc = x + (size_t)toks[row0] * D_DIM + kh;
    const float* wsrc = (row0 < 64) ? wg : wu;
    const float* bsrc = wsrc + (size_t)e * D_DIM * F_DIM + (f0 + (row0 & 63));

    float4 apf[4];
    float  bpf[16];
    const int NS = D_DIM / 32;

    // prefetch stage 0
#pragma unroll
    for (int j = 0; j < 4; ++j) apf[j] = *(const float4*)(asrc + 4 * j);
#pragma unroll
    for (int j = 0; j < 16; ++j) bpf[j] = bsrc[(size_t)(kh + j) * F_DIM];

    for (int s = 0; s < NS; ++s) {
        // split prefetched data and store to smem
        uint32_t ah8[8], al8[8], bh8[8], bl8[8];
#pragma unroll
        for (int j = 0; j < 4; ++j) split4(apf[j], ah8 + 2 * j, al8 + 2 * j);
#pragma unroll
        for (int j = 0; j < 8; ++j) split2(bpf[2 * j], bpf[2 * j + 1], bh8 + j, bl8 + j);
        *(uint4*)&As_h[row0][kh]     = *(uint4*)(ah8);
        *(uint4*)&As_h[row0][kh + 8] = *(uint4*)(ah8 + 4);
        *(uint4*)&As_l[row0][kh]     = *(uint4*)(al8);
        *(uint4*)&As_l[row0][kh + 8] = *(uint4*)(al8 + 4);
        *(uint4*)&Bs_h[row0][kh]     = *(uint4*)(bh8);
        *(uint4*)&Bs_h[row0][kh + 8] = *(uint4*)(bh8 + 4);
        *(uint4*)&Bs_l[row0][kh]     = *(uint4*)(bl8);
        *(uint4*)&Bs_l[row0][kh + 8] = *(uint4*)(bl8 + 4);
        __syncthreads();

        // prefetch next stage into registers (latency hidden behind compute)
        if (s + 1 < NS) {
            int kn = (s + 1) * 32;
#pragma unroll
            for (int j = 0; j < 4; ++j) apf[j] = *(const float4*)(asrc + kn + 4 * j);
#pragma unroll
            for (int j = 0; j < 16; ++j) bpf[j] = bsrc[(size_t)(kn + kh + j) * F_DIM];
        }

        // compute (identical fragment math to R5)
#pragma unroll
        for (int kk = 0; kk < 2; ++kk) {
            int kc = kk * 16 + (lid & 3) * 2;
            uint32_t ah[2][4], al[2][4];
#pragma unroll
            for (int mi = 0; mi < 2; ++mi) {
                int r = wm * 32 + mi * 16 + (lid >> 2);
                ah[mi][0] = *(uint32_t*)&As_h[r][kc];
                ah[mi][1] = *(uint32_t*)&As_h[r + 8][kc];
                ah[mi][2] = *(uint32_t*)&As_h[r][kc + 8];
                ah[mi][3] = *(uint32_t*)&As_h[r + 8][kc + 8];
                al[mi][0] = *(uint32_t*)&As_l[r][kc];
                al[mi][1] = *(uint32_t*)&As_l[r + 8][kc];
                al[mi][2] = *(uint32_t*)&As_l[r][kc + 8];
                al[mi][3] = *(uint32_t*)&As_l[r + 8][kc + 8];
            }
#pragma unroll
            for (int j = 0; j < 4; ++j) {
                int ng = wn * 32 + j * 8 + (lid >> 2);
                uint32_t bgh[2], bgl[2], buh[2], bul[2];
                bgh[0] = *(uint32_t*)&Bs_h[ng][kc];
                bgh[1] = *(uint32_t*)&Bs_h[ng][kc + 8];
                bgl[0] = *(uint32_t*)&Bs_l[ng][kc];
                bgl[1] = *(uint32_t*)&Bs_l[ng][kc + 8];
                buh[0] = *(uint32_t*)&Bs_h[ng + 64][kc];
                buh[1] = *(uint32_t*)&Bs_h[ng + 64][kc + 8];
                bul[0] = *(uint32_t*)&Bs_l[ng + 64][kc];
                bul[1] = *(uint32_t*)&Bs_l[ng + 64][kc + 8];
#pragma unroll
                for (int mi = 0; mi < 2; ++mi) {
                    mma16816(acc_g[mi][j], ah[mi], bgh);
                    mma16816(acc_g[mi][j], ah[mi], bgl);
                    mma16816(acc_g[mi][j], al[mi], bgh);
                    mma16816(acc_u[mi][j], ah[mi], buh);
                    mma16816(acc_u[mi][j], ah[mi], bul);
                    mma16816(acc_u[mi][j], al[mi], buh);
                }
            }
        }
        __syncthreads();
    }

    // epilogue: silu(g)*u, write H fp32 (identical to R5)
#pragma unroll
    for (int mi = 0; mi < 2; ++mi) {
#pragma unroll
        for (int j = 0; j < 4; ++j) {
            int row = m0 + wm * 32 + mi * 16 + (lid >> 2);
            int col = f0 + wn * 32 + j * 8 + (lid & 3) * 2;
#pragma unroll
            for (int half = 0; half < 2; ++half) {
                int r = row + half * 8;
                if (r < cnt) {
                    float g0 = acc_g[mi][j][half * 2 + 0];
                    float g1 = acc_g[mi][j][half * 2 + 1];
                    float u0 = acc_u[mi][j][half * 2 + 0];
                    float u1 = acc_u[mi][j][half * 2 + 1];
                    float2 h;
                    h.x = u0 * g0 / (1.f + __expf(-g0));
                    h.y = u1 * g1 / (1.f + __expf(-g1));
                    *(float2*)&g_H[(size_t)(base + r) * F_DIM + col] = h;
                }
            }
        }
    }
}

// ---------------- GEMM2: O = H @ Wd (Wd native [e][f][d]) ----------------
__global__ void __launch_bounds__(256) gemm2_mma(const float* __restrict__ wd) {
    int e = blockIdx.z;
    int cnt = g_cnt[e];
    int m0 = blockIdx.y * 128;
    if (m0 >= cnt) return;
    int base = g_off[e];
    int n0 = blockIdx.x * 128;

    __shared__ unsigned short As_h[128][PADK], As_l[128][PADK];
    __shared__ unsigned short Bs_h[128][PADK], Bs_l[128][PADK];

    int tid = threadIdx.x;
    int lid = tid & 31, wid = tid >> 5;
    int wm = wid >> 1, wn = wid & 1;

    float acc[2][8][4];
#pragma unroll
    for (int a = 0; a < 2; a++)
#pragma unroll
        for (int b = 0; b < 8; b++)
#pragma unroll
            for (int c = 0; c < 4; c++) acc[a][b][c] = 0.f;

    int row0 = tid >> 1, kh = (tid & 1) * 16;
    int am = m0 + row0;
    const float* asrc = g_H + (size_t)(base + ((am < cnt) ? am : 0)) * F_DIM + kh;
    const float* bsrc = wd + (size_t)e * F_DIM * D_DIM + (n0 + row0);

    float4 apf[4];
    float  bpf[16];
    const int NS = F_DIM / 32;

#pragma unroll
    for (int j = 0; j < 4; ++j) apf[j] = *(const float4*)(asrc + 4 * j);
#pragma unroll
    for (int j = 0; j < 16; ++j) bpf[j] = bsrc[(size_t)(kh + j) * D_DIM];

    for (int s = 0; s < NS; ++s) {
        uint32_t ah8[8], al8[8], bh8[8], bl8[8];
#pragma unroll
        for (int j = 0; j < 4; ++j) split4(apf[j], ah8 + 2 * j, al8 + 2 * j);
#pragma unroll
        for (int j = 0; j < 8; ++j) split2(bpf[2 * j], bpf[2 * j + 1], bh8 + j, bl8 + j);
        *(uint4*)&As_h[row0][kh]     = *(uint4*)(ah8);
        *(uint4*)&As_h[row0][kh + 8] = *(uint4*)(ah8 + 4);
        *(uint4*)&As_l[row0][kh]     = *(uint4*)(al8);
        *(uint4*)&As_l[row0][kh + 8] = *(uint4*)(al8 + 4);
        *(uint4*)&Bs_h[row0][kh]     = *(uint4*)(bh8);
        *(uint4*)&Bs_h[row0][kh + 8] = *(uint4*)(bh8 + 4);
        *(uint4*)&Bs_l[row0][kh]     = *(uint4*)(bl8);
        *(uint4*)&Bs_l[row0][kh + 8] = *(uint4*)(bl8 + 4);
        __syncthreads();

        if (s + 1 < NS) {
            int kn = (s + 1) * 32;
#pragma unroll
            for (int j = 0; j < 4; ++j) apf[j] = *(const float4*)(asrc + kn + 4 * j);
#pragma unroll
            for (int j = 0; j < 16; ++j) bpf[j] = bsrc[(size_t)(kn + kh + j) * D_DIM];
        }

#pragma unroll
        for (int kk = 0; kk < 2; ++kk) {
            int kc = kk * 16 + (lid & 3) * 2;
            uint32_t ah[2][4], al[2][4];
#pragma unroll
            for (int mi = 0; mi < 2; ++mi) {
                int r = wm * 32 + mi * 16 + (lid >> 2);
                ah[mi][0] = *(uint32_t*)&As_h[r][kc];
                ah[mi][1] = *(uint32_t*)&As_h[r + 8][kc];
                ah[mi][2] = *(uint32_t*)&As_h[r][kc + 8];
                ah[mi][3] = *(uint32_t*)&As_h[r + 8][kc + 8];
                al[mi][0] = *(uint32_t*)&As_l[r][kc];
                al[mi][1] = *(uint32_t*)&As_l[r + 8][kc];
                al[mi][2] = *(uint32_t*)&As_l[r][kc + 8];
                al[mi][3] = *(uint32_t*)&As_l[r + 8][kc + 8];
            }
#pragma unroll
            for (int j = 0; j < 8; ++j) {
                int n = wn * 64 + j * 8 + (lid >> 2);
                uint32_t bh[2], bl[2];
                bh[0] = *(uint32_t*)&Bs_h[n][kc];
                bh[1] = *(uint32_t*)&Bs_h[n][kc + 8];
                bl[0] = *(uint32_t*)&Bs_l[n][kc];
                bl[1] = *(uint32_t*)&Bs_l[n][kc + 8];
#pragma unroll
                for (int mi = 0; mi < 2; ++mi) {
                    mma16816(acc[mi][j], ah[mi], bh);
                    mma16816(acc[mi][j], ah[mi], bl);
                    mma16816(acc[mi][j], al[mi], bh);
                }
            }
        }
        __syncthreads();
    }

#pragma unroll
    for (int mi = 0; mi < 2; ++mi) {
#pragma unroll
        for (int j = 0; j < 8; ++j) {
            int row = m0 + wm * 32 + mi * 16 + (lid >> 2);
            int col = n0 + wn * 64 + j * 8 + (lid & 3) * 2;
#pragma unroll
            for (int half = 0; half < 2; ++half) {
                int r = row + half * 8;
                if (r < cnt) {
                    float2 v = make_float2(acc[mi][j][half * 2 + 0],
                                           acc[mi][j][half * 2 + 1]);
                    *(float2*)&g_O[(size_t)(base + r) * D_DIM + col] = v;
                }
            }
        }
    }
}

// ---------------- combine (proven) ----------------
__global__ void combine_kernel(float* __restrict__ out) {
    int idx = blockIdx.x * blockDim.x + threadIdx.x;
    int t = idx / (D_DIM / 4);
    int j4 = (idx % (D_DIM / 4)) * 4;
    float p0 = g_topk_p[t * 2 + 0];
    float p1 = g_topk_p[t * 2 + 1];
    int q0 = g_pair_pos[t * 2 + 0];
    int q1 = g_pair_pos[t * 2 + 1];
    float4 a = *(const float4*)(g_O + (size_t)q0 * D_DIM + j4);
    float4 b = *(const float4*)(g_O + (size_t)q1 * D_DIM + j4);
    float4 o;
    o.x = p0 * a.x + p1 * b.x;
    o.y = p0 * a.y + p1 * b.y;
    o.z = p0 * a.z + p1 * b.z;
    o.w = p0 * a.w + p1 * b.w;
    *(float4*)(out + (size_t)t * D_DIM + j4) = o;
}

extern "C" void kernel_launch(void* const* d_in, const int* in_sizes, int n_in,
                              void* d_out, int out_size) {
    const float* x  = (const float*)d_in[0];
    const float* wr = (const float*)d_in[1];
    const float* wg = (const float*)d_in[2];
    const float* wu = (const float*)d_in[3];
    const float* wd = (const float*)d_in[4];
    float* out = (float*)d_out;

    init_kernel<<<1, 32>>>();
    router_kernel<<<T_TOK, 128>>>(x, wr);
    prefix_kernel<<<1, 32>>>();
    scatter_kernel<<<T_TOK / 256, 256>>>();

    gemm1_mma<<<dim3(F_DIM / 64, NPAIR / 128, E_EXP), 256>>>(x, wg, wu);
    gemm2_mma<<<dim3(D_DIM / 128, NPAIR / 128, E_EXP), 256>>>(wd);

    combine_kernel<<<(T_TOK * D_DIM / 4) / 256, 256>>>(out);
}

// round 8
// speedup vs baseline: 2.2630x; 1.0590x over previous
#include <cuda_runtime.h>
#include <cuda_bf16.h>
#include <stdint.h>

#define T_TOK 8192
#define D_DIM 1024
#define E_EXP 8
#define F_DIM 512
#define NPAIR (T_TOK * 2)

// ---------------- device scratch (R5/R7-proven footprint ~101MB) ----------------
__device__ int   g_topk_idx[NPAIR];
__device__ float g_topk_p[NPAIR];
__device__ int   g_cnt[E_EXP];
__device__ int   g_off[E_EXP];
__device__ int   g_cur[E_EXP];
__device__ int   g_pair_token[NPAIR];
__device__ int   g_pair_pos[NPAIR];
__device__ __align__(256) __nv_bfloat16 g_H_hi[(size_t)(NPAIR + 128) * F_DIM];  // 16.5 MB
__device__ __align__(256) __nv_bfloat16 g_H_lo[(size_t)(NPAIR + 128) * F_DIM];  // 16.5 MB
__device__ float g_O[(size_t)NPAIR * D_DIM];                                    // 64 MB

// ---------------- helpers ----------------
__device__ __forceinline__ uint32_t smem_u32(const void* p) {
    uint32_t a;
    asm("{ .reg .u64 t; cvta.to.shared.u64 t, %1; cvt.u32.u64 %0, t; }"
        : "=r"(a) : "l"(p));
    return a;
}
__device__ __forceinline__ void mma16816(float* c, const uint32_t* a, const uint32_t* b) {
    asm volatile(
        "mma.sync.aligned.m16n8k16.row.col.f32.bf16.bf16.f32 "
        "{%0,%1,%2,%3}, {%4,%5,%6,%7}, {%8,%9}, {%0,%1,%2,%3};"
        : "+f"(c[0]), "+f"(c[1]), "+f"(c[2]), "+f"(c[3])
        : "r"(a[0]), "r"(a[1]), "r"(a[2]), "r"(a[3]), "r"(b[0]), "r"(b[1]));
}
__device__ __forceinline__ void ldsm4(uint32_t* r, uint32_t addr) {
    asm volatile("ldmatrix.sync.aligned.m8n8.x4.shared.b16 {%0,%1,%2,%3}, [%4];"
        : "=r"(r[0]), "=r"(r[1]), "=r"(r[2]), "=r"(r[3]) : "r"(addr));
}
// packed split: (a,b) -> hi bf16x2 + lo bf16x2 (residual)
__device__ __forceinline__ void split2(float a, float b, uint32_t* hi, uint32_t* lo) {
    __nv_bfloat162 h = __float22bfloat162_rn(make_float2(a, b));
    float2 hf = __bfloat1622float2(h);
    __nv_bfloat162 l = __float22bfloat162_rn(make_float2(a - hf.x, b - hf.y));
    *hi = *reinterpret_cast<uint32_t*>(&h);
    *lo = *reinterpret_cast<uint32_t*>(&l);
}
__device__ __forceinline__ void split4(float4 v, uint32_t* hi2, uint32_t* lo2) {
    split2(v.x, v.y, hi2 + 0, lo2 + 0);
    split2(v.z, v.w, hi2 + 1, lo2 + 1);
}

// ---------------- small kernels (proven) ----------------
__global__ void init_kernel() {
    if (threadIdx.x < E_EXP) g_cnt[threadIdx.x] = 0;
}

__global__ void router_kernel(const float* __restrict__ x,
                              const float* __restrict__ wr) {
    int t = blockIdx.x;
    int tid = threadIdx.x;
    float acc[E_EXP];
#pragma unroll
    for (int e = 0; e < E_EXP; e++) acc[e] = 0.f;
    const float* xr = x + (size_t)t * D_DIM;
    for (int i = tid; i < D_DIM; i += 128) {
        float xv = xr[i];
#pragma unroll
        for (int e = 0; e < E_EXP; e++) acc[e] += xv * wr[e * D_DIM + i];
    }
    __shared__ float sh[E_EXP][128];
#pragma unroll
    for (int e = 0; e < E_EXP; e++) sh[e][tid] = acc[e];
    __syncthreads();
    for (int s = 64; s > 0; s >>= 1) {
        if (tid < s) {
#pragma unroll
            for (int e = 0; e < E_EXP; e++) sh[e][tid] += sh[e][tid + s];
        }
        __syncthreads();
    }
    if (tid == 0) {
        float l[E_EXP];
#pragma unroll
        for (int e = 0; e < E_EXP; e++) l[e] = sh[e][0];
        int i1 = 0;
#pragma unroll
        for (int e = 1; e < E_EXP; e++) if (l[e] > l[i1]) i1 = e;
        int i2 = (i1 == 0) ? 1 : 0;
#pragma unroll
        for (int e = 0; e < E_EXP; e++) if (e != i1 && l[e] > l[i2]) i2 = e;
        float ex = __expf(l[i2] - l[i1]);
        float inv = 1.f / (1.f + ex);
        g_topk_idx[t * 2 + 0] = i1; g_topk_p[t * 2 + 0] = inv;
        g_topk_idx[t * 2 + 1] = i2; g_topk_p[t * 2 + 1] = ex * inv;
        atomicAdd(&g_cnt[i1], 1);
        atomicAdd(&g_cnt[i2], 1);
    }
}

__global__ void prefix_kernel() {
    if (threadIdx.x == 0) {
        int acc = 0;
        for (int e = 0; e < E_EXP; e++) { g_off[e] = acc; g_cur[e] = acc; acc += g_cnt[e]; }
    }
}

__global__ void scatter_kernel() {
    int t = blockIdx.x * blockDim.x + threadIdx.x;
    if (t >= T_TOK) return;
#pragma unroll
    for (int k = 0; k < 2; k++) {
        int e = g_topk_idx[t * 2 + k];
        int pos = atomicAdd(&g_cur[e], 1);
        g_pair_token[pos] = t;
        g_pair_pos[t * 2 + k] = pos;
    }
}

// smem tile: 128 rows x 32 bf16, rows padded to 40 shorts (80B).
// ldmatrix 8-row phases with 80B stride cover all 32 banks exactly once.
#define PADK 40

// ---------------- GEMM1: H = silu(X Wg) * (X Wu) ----------------
__global__ void __launch_bounds__(256) gemm1_mma(const float* __restrict__ x,
                                                 const float* __restrict__ wg,
                                                 const float* __restrict__ wu) {
    int e = blockIdx.z;
    int cnt = g_cnt[e];
    int m0 = blockIdx.y * 128;
    if (m0 >= cnt) return;
    int base = g_off[e];
    int f0 = blockIdx.x * 64;

    __shared__ unsigned short As_h[128][PADK], As_l[128][PADK];
    __shared__ unsigned short Bs_h[128][PADK], Bs_l[128][PADK];
    __shared__ int toks[128];

    int tid = threadIdx.x;
    int lid = tid & 31, wid = tid >> 5;
    int wm = wid >> 1, wn = wid & 1;

    if (tid < 128) {
        int m = m0 + tid;
        toks[tid] = g_pair_token[base + ((m < cnt) ? m : 0)];
    }
    __syncthreads();

    uint32_t aH = smem_u32(As_h), aL = smem_u32(As_l);
    uint32_t bH = smem_u32(Bs_h), bL = smem_u32(Bs_l);

    // ldmatrix lane mapping (verified against R5 direct-LDS fragment layout)
    int grp = lid >> 3, lr = lid & 7;
    // A: bytes; + mi*16*PADK*2 + kk*32
    uint32_t aofs = (uint32_t)(((wm * 32 + (grp & 1) * 8 + lr) * PADK + (grp >> 1) * 8) * 2);
    // B: bytes; + jj*16*PADK*2 + kk*32 ; up tile at +64 rows
    uint32_t bofs = (uint32_t)(((wn * 32 + (grp >> 1) * 8 + lr) * PADK + (grp & 1) * 8) * 2);

    float acc_g[2][4][4], acc_u[2][4][4];
#pragma unroll
    for (int a = 0; a < 2; a++)
#pragma unroll
        for (int b = 0; b < 4; b++)
#pragma unroll
            for (int c = 0; c < 4; c++) { acc_g[a][b][c] = 0.f; acc_u[a][b][c] = 0.f; }

    int row0 = tid >> 1, kh = (tid & 1) * 16;
    const float* asrc = x + (size_t)toks[row0] * D_DIM + kh;
    const float* wsrc = (row0 < 64) ? wg : wu;
    const float* bsrc = wsrc + (size_t)e * D_DIM * F_DIM + (f0 + (row0 & 63));

    float4 apf[4];
    float  bpf[16];
    const int NS = D_DIM / 32;

#pragma unroll
    for (int j = 0; j < 4; ++j) apf[j] = *(const float4*)(asrc + 4 * j);
#pragma unroll
    for (int j = 0; j < 16; ++j) bpf[j] = bsrc[(size_t)(kh + j) * F_DIM];

    for (int s = 0; s < NS; ++s) {
        uint32_t ah8[8], al8[8], bh8[8], bl8[8];
#pragma unroll
        for (int j = 0; j < 4; ++j) split4(apf[j], ah8 + 2 * j, al8 + 2 * j);
#pragma unroll
        for (int j = 0; j < 8; ++j) split2(bpf[2 * j], bpf[2 * j + 1], bh8 + j, bl8 + j);
        *(uint4*)&As_h[row0][kh]     = *(uint4*)(ah8);
        *(uint4*)&As_h[row0][kh + 8] = *(uint4*)(ah8 + 4);
        *(uint4*)&As_l[row0][kh]     = *(uint4*)(al8);
        *(uint4*)&As_l[row0][kh + 8] = *(uint4*)(al8 + 4);
        *(uint4*)&Bs_h[row0][kh]     = *(uint4*)(bh8);
        *(uint4*)&Bs_h[row0][kh + 8] = *(uint4*)(bh8 + 4);
        *(uint4*)&Bs_l[row0][kh]     = *(uint4*)(bl8);
        *(uint4*)&Bs_l[row0][kh + 8] = *(uint4*)(bl8 + 4);
        __syncthreads();

        if (s + 1 < NS) {
            int kn = (s + 1) * 32;
#pragma unroll
            for (int j = 0; j < 4; ++j) apf[j] = *(const float4*)(asrc + kn + 4 * j);
#pragma unroll
            for (int j = 0; j < 16; ++j) bpf[j] = bsrc[(size_t)(kn + kh + j) * F_DIM];
        }

#pragma unroll
        for (int kk = 0; kk < 2; ++kk) {
            uint32_t ah[2][4], al[2][4];
#pragma unroll
            for (int mi = 0; mi < 2; ++mi) {
                uint32_t ao = aofs + (uint32_t)(mi * 16 * PADK * 2 + kk * 32);
                ldsm4(ah[mi], aH + ao);
                ldsm4(al[mi], aL + ao);
            }
#pragma unroll
            for (int jj = 0; jj < 2; ++jj) {
                uint32_t bo = bofs + (uint32_t)(jj * 16 * PADK * 2 + kk * 32);
                uint32_t gh[4], gl[4], uh[4], ul[4];
                ldsm4(gh, bH + bo);
                ldsm4(gl, bL + bo);
                ldsm4(uh, bH + bo + 64 * PADK * 2);
                ldsm4(ul, bL + bo + 64 * PADK * 2);
#pragma unroll
                for (int jo = 0; jo < 2; ++jo) {
                    int j = jj * 2 + jo;
#pragma unroll
                    for (int mi = 0; mi < 2; ++mi) {
                        mma16816(acc_g[mi][j], ah[mi], gh + jo * 2);
                        mma16816(acc_g[mi][j], ah[mi], gl + jo * 2);
                        mma16816(acc_g[mi][j], al[mi], gh + jo * 2);
                        mma16816(acc_u[mi][j], ah[mi], uh + jo * 2);
                        mma16816(acc_u[mi][j], ah[mi], ul + jo * 2);
                        mma16816(acc_u[mi][j], al[mi], uh + jo * 2);
                    }
                }
            }
        }
        __syncthreads();
    }

    // epilogue: silu(g)*u, split once, write bf16 hi/lo H
#pragma unroll
    for (int mi = 0; mi < 2; ++mi) {
#pragma unroll
        for (int j = 0; j < 4; ++j) {
            int row = m0 + wm * 32 + mi * 16 + (lid >> 2);
            int col = f0 + wn * 32 + j * 8 + (lid & 3) * 2;
#pragma unroll
            for (int half = 0; half < 2; ++half) {
                int r = row + half * 8;
                if (r < cnt) {
                    float g0 = acc_g[mi][j][half * 2 + 0];
                    float g1 = acc_g[mi][j][half * 2 + 1];
                    float u0 = acc_u[mi][j][half * 2 + 0];
                    float u1 = acc_u[mi][j][half * 2 + 1];
                    float h0 = u0 * g0 / (1.f + __expf(-g0));
                    float h1 = u1 * g1 / (1.f + __expf(-g1));
                    uint32_t hi, lo;
                    split2(h0, h1, &hi, &lo);
                    size_t o = (size_t)(base + r) * F_DIM + col;
                    *(uint32_t*)&g_H_hi[o] = hi;
                    *(uint32_t*)&g_H_lo[o] = lo;
                }
            }
        }
    }
}

// ---------------- GEMM2: O = H @ Wd (Wd native [e][f][d]) ----------------
__global__ void __launch_bounds__(256) gemm2_mma(const float* __restrict__ wd) {
    int e = blockIdx.z;
    int cnt = g_cnt[e];
    int m0 = blockIdx.y * 128;
    if (m0 >= cnt) return;
    int base = g_off[e];
    int n0 = blockIdx.x * 128;

    __shared__ unsigned short As_h[128][PADK], As_l[128][PADK];
    __shared__ unsigned short Bs_h[128][PADK], Bs_l[128][PADK];

    int tid = threadIdx.x;
    int lid = tid & 31, wid = tid >> 5;
    int wm = wid >> 1, wn = wid & 1;

    uint32_t aH = smem_u32(As_h), aL = smem_u32(As_l);
    uint32_t bH = smem_u32(Bs_h), bL = smem_u32(Bs_l);

    int grp = lid >> 3, lr = lid & 7;
    uint32_t aofs = (uint32_t)(((wm * 32 + (grp & 1) * 8 + lr) * PADK + (grp >> 1) * 8) * 2);
    uint32_t bofs = (uint32_t)(((wn * 64 + (grp >> 1) * 8 + lr) * PADK + (grp & 1) * 8) * 2);

    float acc[2][8][4];
#pragma unroll
    for (int a = 0; a < 2; a++)
#pragma unroll
        for (int b = 0; b < 8; b++)
#pragma unroll
            for (int c = 0; c < 4; c++) acc[a][b][c] = 0.f;

    int row0 = tid >> 1, kh = (tid & 1) * 16;
    int am = m0 + row0;
    size_t arow = (size_t)(base + ((am < cnt) ? am : 0)) * F_DIM + kh;
    const float* bsrc = wd + (size_t)e * F_DIM * D_DIM + (n0 + row0);

    uint4 aph[2], apl[2];
    float bpf[16];
    const int NS = F_DIM / 32;

#pragma unroll
    for (int j = 0; j < 2; ++j) {
        aph[j] = *(const uint4*)(g_H_hi + arow + 8 * j);
        apl[j] = *(const uint4*)(g_H_lo + arow + 8 * j);
    }
#pragma unroll
    for (int j = 0; j < 16; ++j) bpf[j] = bsrc[(size_t)(kh + j) * D_DIM];

    for (int s = 0; s < NS; ++s) {
        uint32_t bh8[8], bl8[8];
#pragma unroll
        for (int j = 0; j < 8; ++j) split2(bpf[2 * j], bpf[2 * j + 1], bh8 + j, bl8 + j);
        *(uint4*)&As_h[row0][kh]     = aph[0];
        *(uint4*)&As_h[row0][kh + 8] = aph[1];
        *(uint4*)&As_l[row0][kh]     = apl[0];
        *(uint4*)&As_l[row0][kh + 8] = apl[1];
        *(uint4*)&Bs_h[row0][kh]     = *(uint4*)(bh8);
        *(uint4*)&Bs_h[row0][kh + 8] = *(uint4*)(bh8 + 4);
        *(uint4*)&Bs_l[row0][kh]     = *(uint4*)(bl8);
        *(uint4*)&Bs_l[row0][kh + 8] = *(uint4*)(bl8 + 4);
        __syncthreads();

        if (s + 1 < NS) {
            int kn = (s + 1) * 32;
#pragma unroll
            for (int j = 0; j < 2; ++j) {
                aph[j] = *(const uint4*)(g_H_hi + arow + kn + 8 * j);
                apl[j] = *(const uint4*)(g_H_lo + arow + kn + 8 * j);
            }
#pragma unroll
            for (int j = 0; j < 16; ++j) bpf[j] = bsrc[(size_t)(kn + kh + j) * D_DIM];
        }

#pragma unroll
        for (int kk = 0; kk < 2; ++kk) {
            uint32_t ah[2][4], al[2][4];
#pragma unroll
            for (int mi = 0; mi < 2; ++mi) {
                uint32_t ao = aofs + (uint32_t)(mi * 16 * PADK * 2 + kk * 32);
                ldsm4(ah[mi], aH + ao);
                ldsm4(al[mi], aL + ao);
            }
#pragma unroll
            for (int jj = 0; jj < 4; ++jj) {
                uint32_t bo = bofs + (uint32_t)(jj * 16 * PADK * 2 + kk * 32);
                uint32_t bh[4], bl[4];
                ldsm4(bh, bH + bo);
                ldsm4(bl, bL + bo);
#pragma unroll
                for (int jo = 0; jo < 2; ++jo) {
                    int j = jj * 2 + jo;
#pragma unroll
                    for (int mi = 0; mi < 2; ++mi) {
                        mma16816(acc[mi][j], ah[mi], bh + jo * 2);
                        mma16816(acc[mi][j], ah[mi], bl + jo * 2);
                        mma16816(acc[mi][j], al[mi], bh + jo * 2);
                    }
                }
            }
        }
        __syncthreads();
    }

#pragma unroll
    for (int mi = 0; mi < 2; ++mi) {
#pragma unroll
        for (int j = 0; j < 8; ++j) {
            int row = m0 + wm * 32 + mi * 16 + (lid >> 2);
            int col = n0 + wn * 64 + j * 8 + (lid & 3) * 2;
#pragma unroll
            for (int half = 0; half < 2; ++half) {
                int r = row + half * 8;
                if (r < cnt) {
                    float2 v = make_float2(acc[mi][j][half * 2 + 0],
                                           acc[mi][j][half * 2 + 1]);
                    *(float2*)&g_O[(size_t)(base + r) * D_DIM + col] = v;
                }
            }
        }
    }
}

// ---------------- combine (proven) ----------------
__global__ void combine_kernel(float* __restrict__ out) {
    int idx = blockIdx.x * blockDim.x + threadIdx.x;
    int t = idx / (D_DIM / 4);
    int j4 = (idx % (D_DIM / 4)) * 4;
    float p0 = g_topk_p[t * 2 + 0];
    float p1 = g_topk_p[t * 2 + 1];
    int q0 = g_pair_pos[t * 2 + 0];
    int q1 = g_pair_pos[t * 2 + 1];
    float4 a = *(const float4*)(g_O + (size_t)q0 * D_DIM + j4);
    float4 b = *(const float4*)(g_O + (size_t)q1 * D_DIM + j4);
    float4 o;
    o.x = p0 * a.x + p1 * b.x;
    o.y = p0 * a.y + p1 * b.y;
    o.z = p0 * a.z + p1 * b.z;
    o.w = p0 * a.w + p1 * b.w;
    *(float4*)(out + (size_t)t * D_DIM + j4) = o;
}

extern "C" void kernel_launch(void* const* d_in, const int* in_sizes, int n_in,
                              void* d_out, int out_size) {
    const float* x  = (const float*)d_in[0];
    const float* wr = (const float*)d_in[1];
    const float* wg = (const float*)d_in[2];
    const float* wu = (const float*)d_in[3];
    const float* wd = (const float*)d_in[4];
    float* out = (float*)d_out;

    init_kernel<<<1, 32>>>();
    router_kernel<<<T_TOK, 128>>>(x, wr);
    prefix_kernel<<<1, 32>>>();
    scatter_kernel<<<T_TOK / 256, 256>>>();

    gemm1_mma<<<dim3(F_DIM / 64, NPAIR / 128, E_EXP), 256>>>(x, wg, wu);
    gemm2_mma<<<dim3(D_DIM / 128, NPAIR / 128, E_EXP), 256>>>(wd);

    combine_kernel<<<(T_TOK * D_DIM / 4) / 256, 256>>>(out);
}